// round 2
// baseline (speedup 1.0000x reference)
#include <cuda_runtime.h>
#include <cuda_bf16.h>
#include <math.h>

#define Bn 32
#define Tn 2048
#define In 512
#define Hn 512
#define Ln 4
#define Gn 2048

#define NCTA 128
#define TPB 128
#define UNITS 4
#define ROWS 16
#define KTOT 1024
#define WPITCH 1028

#define SMEM_FLOATS (ROWS * WPITCH + KTOT * Bn + ROWS * Bn + ROWS)
#define SMEM_BYTES (SMEM_FLOATS * 4)

// Static scratch (no runtime allocation)
__device__ float g_xT[(size_t)Tn * In * Bn];        // x transposed: [t][i][b]
__device__ float g_hT[2][(size_t)Tn * Hn * Bn];     // ping-pong layer outputs: [t][j][b]
__device__ unsigned g_flags[NCTA];

__global__ void init_kernel() {
  if (threadIdx.x < NCTA) g_flags[threadIdx.x] = 0u;
}

// x (B,T,I) -> g_xT [t][i][b]; coalesced both sides
__global__ void transpose_x_kernel(const float* __restrict__ x) {
  __shared__ float tile[32][33];
  const int i0 = blockIdx.x * 32;
  const int t = blockIdx.y;
  const int lane = threadIdx.x;
  const int ty = threadIdx.y;
#pragma unroll
  for (int bo = 0; bo < 32; bo += 8) {
    int b = bo + ty;
    tile[b][lane] = x[((size_t)b * Tn + t) * In + (i0 + lane)];
  }
  __syncthreads();
#pragma unroll
  for (int io = 0; io < 32; io += 8) {
    int i = io + ty;
    g_xT[((size_t)t * In + (i0 + i)) * Bn + lane] = tile[lane][i];
  }
}

__device__ __forceinline__ float sigm(float v) {
  return 1.0f / (1.0f + __expf(-v));
}

__global__ void __launch_bounds__(TPB, 1) lstm_persistent_kernel(
    const float* __restrict__ h0, const float* __restrict__ c0,
    const float* __restrict__ w_ih, const float* __restrict__ w_hh,
    const float* __restrict__ b_ih, const float* __restrict__ b_hh,
    float* __restrict__ out)
{
  extern __shared__ float smem[];
  float* Wsh = smem;                    // [ROWS][WPITCH]
  float* zsh = Wsh + ROWS * WPITCH;     // [KTOT][Bn]
  float* pre = zsh + KTOT * Bn;         // [ROWS][Bn]
  float* bsh = pre + ROWS * Bn;         // [ROWS]

  const int tid = threadIdx.x;
  const int ct = blockIdx.x;
  // GEMM mapping: one gate-row, 4 batches per thread
  const int r = tid >> 3;               // 0..15
  const int bq = tid & 7;               // 0..7 (batch quad)
  // gate mapping: one (unit, batch) per thread
  const int ju = tid >> 5;              // 0..3
  const int bb = tid & 31;              // 0..31
  const int unit = ct * UNITS + ju;

  for (int l = 0; l < Ln; ++l) {
    // ---- load this CTA's weight slice into SMEM (concat [Wih | Whh])
    const float* Wih = w_ih + (size_t)l * Gn * In;
    const float* Whh = w_hh + (size_t)l * Gn * Hn;
    for (int idx = tid; idx < ROWS * (KTOT / 4); idx += TPB) {
      int rr = idx >> 8;                // local row 0..15
      int k = (idx & 255) << 2;         // 0..1020
      int q = rr >> 2, juu = rr & 3;
      int gr = q * Hn + ct * UNITS + juu;   // global gate row
      float4 v;
      if (k < In) v = *reinterpret_cast<const float4*>(Wih + (size_t)gr * In + k);
      else        v = *reinterpret_cast<const float4*>(Whh + (size_t)gr * Hn + (k - In));
      *reinterpret_cast<float4*>(Wsh + rr * WPITCH + k) = v;
    }
    if (tid < ROWS) {
      int q = tid >> 2, juu = tid & 3;
      int gr = q * Hn + ct * UNITS + juu;
      bsh[tid] = b_ih[(size_t)l * Gn + gr] + b_hh[(size_t)l * Gn + gr];
    }
    float c = c0[(size_t)l * Bn * Hn + (size_t)bb * Hn + unit];

    const float* xsrc = (l == 0) ? g_xT : g_hT[(l & 1) ^ 1];
    float* hout = g_hT[l & 1];
    __syncthreads();

    for (int t = 0; t < Tn; ++t) {
      // ---- stage z = [x_t ; h_{t-1}] into SMEM (coalesced, L1-bypassed)
      {
        const float4* src = reinterpret_cast<const float4*>(xsrc + (size_t)t * In * Bn);
        float4* zx = reinterpret_cast<float4*>(zsh);
#pragma unroll 4
        for (int idx = tid; idx < (In * Bn) / 4; idx += TPB)
          zx[idx] = __ldcg(src + idx);
      }
      if (t == 0) {
        const float* hsrc = h0 + (size_t)l * Bn * Hn;
        for (int idx = tid; idx < Bn * Hn; idx += TPB) {
          int j = idx >> 5, b = idx & 31;
          zsh[(In + j) * Bn + b] = __ldcg(hsrc + (size_t)b * Hn + j);
        }
      } else {
        const float4* hsrc = reinterpret_cast<const float4*>(hout + (size_t)(t - 1) * Hn * Bn);
        float4* zh = reinterpret_cast<float4*>(zsh + In * Bn);
#pragma unroll 4
        for (int idx = tid; idx < (Hn * Bn) / 4; idx += TPB)
          zh[idx] = __ldcg(hsrc + idx);
      }
      __syncthreads();

      // ---- micro-GEMM: pre[16][32] = Wsh[16][1024] @ zsh[1024][32] (+bias)
      {
        const float* wrow = Wsh + r * WPITCH;
        const float* zq = zsh + (bq << 2);
        float bias = bsh[r];
        float a0 = bias, a1 = bias, a2 = bias, a3 = bias;
#pragma unroll 4
        for (int k = 0; k < KTOT; k += 4) {
          float4 w = *reinterpret_cast<const float4*>(wrow + k);
          float4 z0 = *reinterpret_cast<const float4*>(zq + (size_t)(k + 0) * Bn);
          float4 z1 = *reinterpret_cast<const float4*>(zq + (size_t)(k + 1) * Bn);
          float4 z2 = *reinterpret_cast<const float4*>(zq + (size_t)(k + 2) * Bn);
          float4 z3 = *reinterpret_cast<const float4*>(zq + (size_t)(k + 3) * Bn);
          a0 = fmaf(w.x, z0.x, a0); a1 = fmaf(w.x, z0.y, a1);
          a2 = fmaf(w.x, z0.z, a2); a3 = fmaf(w.x, z0.w, a3);
          a0 = fmaf(w.y, z1.x, a0); a1 = fmaf(w.y, z1.y, a1);
          a2 = fmaf(w.y, z1.z, a2); a3 = fmaf(w.y, z1.w, a3);
          a0 = fmaf(w.z, z2.x, a0); a1 = fmaf(w.z, z2.y, a1);
          a2 = fmaf(w.z, z2.z, a2); a3 = fmaf(w.z, z2.w, a3);
          a0 = fmaf(w.w, z3.x, a0); a1 = fmaf(w.w, z3.y, a1);
          a2 = fmaf(w.w, z3.z, a2); a3 = fmaf(w.w, z3.w, a3);
        }
        float4 res = make_float4(a0, a1, a2, a3);
        *reinterpret_cast<float4*>(pre + r * Bn + (bq << 2)) = res;
      }
      __syncthreads();

      // ---- gates + state update; write h transposed
      {
        float gi = sigm(pre[(0 * UNITS + ju) * Bn + bb]);
        float gf = sigm(pre[(1 * UNITS + ju) * Bn + bb]);
        float gg = tanhf(pre[(2 * UNITS + ju) * Bn + bb]);
        float go = sigm(pre[(3 * UNITS + ju) * Bn + bb]);
        c = gf * c + gi * gg;
        float h = go * tanhf(c);
        hout[((size_t)t * Hn + unit) * Bn + bb] = h;
        if (t == Tn - 1)
          out[(size_t)l * Bn * Hn + (size_t)bb * Hn + unit] = c;
      }

      // ---- grid barrier (flag array + poll), all CTAs resident
      unsigned step_id = (unsigned)(l * Tn + t + 1);
      __threadfence();
      __syncthreads();
      if (tid == 0) *(volatile unsigned*)&g_flags[ct] = step_id;
      bool ok;
      do {
        ok = (*(volatile unsigned*)&g_flags[tid] >= step_id);
      } while (!__syncthreads_and(ok));
    }
  }
}

extern "C" void kernel_launch(void* const* d_in, const int* in_sizes, int n_in,
                              void* d_out, int out_size) {
  const float* x    = (const float*)d_in[0];
  const float* h0   = (const float*)d_in[1];
  const float* c0   = (const float*)d_in[2];
  const float* w_ih = (const float*)d_in[3];
  const float* w_hh = (const float*)d_in[4];
  const float* b_ih = (const float*)d_in[5];
  const float* b_hh = (const float*)d_in[6];
  float* out = (float*)d_out;

  cudaFuncSetAttribute(lstm_persistent_kernel,
                       cudaFuncAttributeMaxDynamicSharedMemorySize, SMEM_BYTES);
  init_kernel<<<1, TPB>>>();
  transpose_x_kernel<<<dim3(In / 32, Tn), dim3(32, 8)>>>(x);
  lstm_persistent_kernel<<<NCTA, TPB, SMEM_BYTES>>>(h0, c0, w_ih, w_hh, b_ih, b_hh, out);
}

// round 3
// speedup vs baseline: 1.5250x; 1.5250x over previous
#include <cuda_runtime.h>
#include <cuda_bf16.h>
#include <math.h>

#define Bn 32
#define Tn 2048
#define In 512
#define Hn 512
#define Ln 4
#define Gn 2048   // 4*H

// ---------------- phase A (xg pre-GEMM) config ----------------
#define GT 256          // threads
#define TR 128          // tile rows (gate rows)
#define TK 32           // k chunk
#define WPAD 132
#define ZPAD 132
#define GEMM_SMEM ((2*TK*WPAD + 2*TK*ZPAD) * 4)

// ---------------- recurrence config ----------------
#define NCTA 128
#define RTPB 256
#define RROWS 16        // gate rows per CTA (4 gates x 4 units)
#define WP 516          // padded W row pitch
#define REC_SMEM ((RROWS*WP + Hn*Bn + 2*RROWS*Bn) * 4)

// Static scratch
__device__ float g_xg[(size_t)Tn * Gn * Bn];       // [t][gate_row][b]
__device__ float g_hT[2][(size_t)Tn * Hn * Bn];    // ping-pong [t][j][b]
__device__ unsigned g_flags[NCTA];

__global__ void init_kernel() {
  if (threadIdx.x < NCTA) g_flags[threadIdx.x] = 0u;
}

// ============ Phase A: xg[t][gr][b] = sum_i W[gr][i]*inp[t][i][b] + bias ============
// mode 0: inp = x, layout (B, T, I). mode 1: inp = g_hT[hin], layout [t][i][b].
__global__ void __launch_bounds__(GT) xg_gemm_kernel(
    const float* __restrict__ W,      // (2048, 512) row-major, layer slice
    const float* __restrict__ bih, const float* __restrict__ bhh,
    const float* __restrict__ x, int mode, int hin)
{
  extern __shared__ float sm[];
  float* Ws = sm;                  // [2][TK][WPAD]  (k-major)
  float* Zs = sm + 2 * TK * WPAD;  // [2][TK][ZPAD]

  const float* inp = mode ? g_hT[hin] : x;
  const int tid = threadIdx.x;
  const int t0 = blockIdx.x * 4;          // 4 timesteps per tile (128 cols)
  const int r0 = blockIdx.y * TR;
  const int trow = tid >> 4;              // 0..15
  const int tcol = tid & 15;              // 0..15

  float acc[8][8];
#pragma unroll
  for (int i = 0; i < 8; i++)
#pragma unroll
    for (int j = 0; j < 8; j++) acc[i][j] = 0.f;

  float4 wr[4], zr[4];

  auto ldg_chunk = [&](int kc) {
#pragma unroll
    for (int j = 0; j < 4; j++) {
      int idx = tid * 4 + j;
      int row = idx >> 3, kq = idx & 7;
      wr[j] = *reinterpret_cast<const float4*>(W + (size_t)(r0 + row) * In + kc + kq * 4);
    }
    if (mode) {
#pragma unroll
      for (int j = 0; j < 4; j++) {
        int kk = (tid >> 5) * 4 + j;
        int colq = tid & 31;
        int tt = colq >> 3, b4 = (colq & 7) * 4;
        zr[j] = *reinterpret_cast<const float4*>(inp + ((size_t)(t0 + tt) * In + kc + kk) * Bn + b4);
      }
    } else {
#pragma unroll
      for (int j = 0; j < 4; j++) {
        int idx = tid * 4 + j;
        int ki = idx & 7, tt = (idx >> 3) & 3, b = idx >> 5;
        zr[j] = *reinterpret_cast<const float4*>(inp + ((size_t)b * Tn + t0 + tt) * In + kc + ki * 4);
      }
    }
  };

  auto sts_chunk = [&](int buf) {
    float* Wb = Ws + buf * TK * WPAD;
    float* Zb = Zs + buf * TK * ZPAD;
#pragma unroll
    for (int j = 0; j < 4; j++) {
      int idx = tid * 4 + j;
      int row = idx >> 3, kq = idx & 7;
      Wb[(kq * 4 + 0) * WPAD + row] = wr[j].x;
      Wb[(kq * 4 + 1) * WPAD + row] = wr[j].y;
      Wb[(kq * 4 + 2) * WPAD + row] = wr[j].z;
      Wb[(kq * 4 + 3) * WPAD + row] = wr[j].w;
    }
    if (mode) {
#pragma unroll
      for (int j = 0; j < 4; j++) {
        int kk = (tid >> 5) * 4 + j;
        int colq = tid & 31;
        *reinterpret_cast<float4*>(Zb + kk * ZPAD + colq * 4) = zr[j];
      }
    } else {
#pragma unroll
      for (int j = 0; j < 4; j++) {
        int idx = tid * 4 + j;
        int ki = idx & 7, tt = (idx >> 3) & 3, b = idx >> 5;
        Zb[(ki * 4 + 0) * ZPAD + tt * 32 + b] = zr[j].x;
        Zb[(ki * 4 + 1) * ZPAD + tt * 32 + b] = zr[j].y;
        Zb[(ki * 4 + 2) * ZPAD + tt * 32 + b] = zr[j].z;
        Zb[(ki * 4 + 3) * ZPAD + tt * 32 + b] = zr[j].w;
      }
    }
  };

  auto compute = [&](int buf) {
    const float* Wb = Ws + buf * TK * WPAD;
    const float* Zb = Zs + buf * TK * ZPAD;
#pragma unroll 8
    for (int kk = 0; kk < TK; kk++) {
      float4 wa = *reinterpret_cast<const float4*>(Wb + kk * WPAD + trow * 8);
      float4 wb2 = *reinterpret_cast<const float4*>(Wb + kk * WPAD + trow * 8 + 4);
      float4 za = *reinterpret_cast<const float4*>(Zb + kk * ZPAD + tcol * 8);
      float4 zb2 = *reinterpret_cast<const float4*>(Zb + kk * ZPAD + tcol * 8 + 4);
      float w8[8] = {wa.x, wa.y, wa.z, wa.w, wb2.x, wb2.y, wb2.z, wb2.w};
      float z8[8] = {za.x, za.y, za.z, za.w, zb2.x, zb2.y, zb2.z, zb2.w};
#pragma unroll
      for (int i = 0; i < 8; i++)
#pragma unroll
        for (int j = 0; j < 8; j++)
          acc[i][j] = fmaf(w8[i], z8[j], acc[i][j]);
    }
  };

  ldg_chunk(0);
  sts_chunk(0);
  __syncthreads();
  const int NCH = In / TK;   // 16
  for (int c = 0; c < NCH; c++) {
    int buf = c & 1;
    if (c + 1 < NCH) ldg_chunk((c + 1) * TK);
    compute(buf);
    __syncthreads();
    if (c + 1 < NCH) {
      sts_chunk(buf ^ 1);
      __syncthreads();
    }
  }

  // epilogue: add bias, write xg[t][row][b]
#pragma unroll
  for (int i = 0; i < 8; i++) {
    int row = r0 + trow * 8 + i;
    float bv = __ldg(bih + row) + __ldg(bhh + row);
    int tt = tcol >> 2;
    int b0 = (tcol & 3) * 8;
    float* dst = g_xg + ((size_t)(t0 + tt) * Gn + row) * Bn + b0;
    float4 v0 = make_float4(acc[i][0] + bv, acc[i][1] + bv, acc[i][2] + bv, acc[i][3] + bv);
    float4 v1 = make_float4(acc[i][4] + bv, acc[i][5] + bv, acc[i][6] + bv, acc[i][7] + bv);
    *reinterpret_cast<float4*>(dst) = v0;
    *reinterpret_cast<float4*>(dst + 4) = v1;
  }
}

// ============ Recurrence: h-path GEMM + gates, persistent per layer ============
__global__ void __launch_bounds__(RTPB, 1) lstm_rec_kernel(
    const float* __restrict__ h0, const float* __restrict__ c0,
    const float* __restrict__ Whh,       // (2048, 512) layer slice
    float* __restrict__ out, int l, int hsel)
{
  extern __shared__ float smem[];
  float* Wsh = smem;                     // [16][WP]
  float* zsh = Wsh + RROWS * WP;         // [512][32]
  float* pre2 = zsh + Hn * Bn;           // [2][16][32] (k-half partials)

  const int tid = threadIdx.x;
  const int ct = blockIdx.x;
  const int khalf = tid >> 7;            // 0/1
  const int sub = tid & 127;
  const int r = sub >> 3;                // 0..15 gate row (local)
  const int bq = sub & 7;                // batch quad
  const int ju = tid >> 5;               // 0..3 (valid for tid<128)
  const int bb = tid & 31;
  const int unit = ct * 4 + ju;

  float* hout = g_hT[hsel];
  const float* xg = g_xg;

  // load Whh slice: Wsh[rr][k] = Whh[q*512 + ct*4 + juu][k]
  for (int idx = tid; idx < RROWS * (Hn / 4); idx += RTPB) {
    int rr = idx >> 7, kq = idx & 127;
    int q = rr >> 2, juu = rr & 3;
    int gr = q * Hn + ct * 4 + juu;
    *reinterpret_cast<float4*>(Wsh + rr * WP + kq * 4) =
        *reinterpret_cast<const float4*>(Whh + (size_t)gr * Hn + kq * 4);
  }
  float c = (tid < 128) ? c0[(size_t)l * Bn * Hn + (size_t)bb * Hn + unit] : 0.f;

  const unsigned base = (unsigned)(l * Tn);

  for (int t = 0; t < Tn; t++) {
    // ---- stage z = h_{t-1} [j][b]
    if (t == 0) {
      const float* hs = h0 + (size_t)l * Bn * Hn;
      for (int idx = tid; idx < Bn * Hn; idx += RTPB) {
        int j = idx >> 5, b = idx & 31;
        zsh[j * Bn + b] = __ldcg(hs + (size_t)b * Hn + j);
      }
    } else {
      const float4* hs = reinterpret_cast<const float4*>(hout + (size_t)(t - 1) * Hn * Bn);
      float4* z4 = reinterpret_cast<float4*>(zsh);
#pragma unroll 4
      for (int idx = tid; idx < (Hn * Bn) / 4; idx += RTPB)
        z4[idx] = __ldcg(hs + idx);
    }
    __syncthreads();

    // ---- half-K GEMM: pre2[khalf][16][32]
    {
      const float* wrow = Wsh + r * WP + khalf * 256;
      const float* zq = zsh + khalf * 256 * Bn + bq * 4;
      float a0 = 0.f, a1 = 0.f, a2 = 0.f, a3 = 0.f;
#pragma unroll 4
      for (int k = 0; k < 256; k += 4) {
        float4 w = *reinterpret_cast<const float4*>(wrow + k);
        float4 z0 = *reinterpret_cast<const float4*>(zq + (size_t)(k + 0) * Bn);
        float4 z1 = *reinterpret_cast<const float4*>(zq + (size_t)(k + 1) * Bn);
        float4 z2 = *reinterpret_cast<const float4*>(zq + (size_t)(k + 2) * Bn);
        float4 z3 = *reinterpret_cast<const float4*>(zq + (size_t)(k + 3) * Bn);
        a0 = fmaf(w.x, z0.x, a0); a1 = fmaf(w.x, z0.y, a1);
        a2 = fmaf(w.x, z0.z, a2); a3 = fmaf(w.x, z0.w, a3);
        a0 = fmaf(w.y, z1.x, a0); a1 = fmaf(w.y, z1.y, a1);
        a2 = fmaf(w.y, z1.z, a2); a3 = fmaf(w.y, z1.w, a3);
        a0 = fmaf(w.z, z2.x, a0); a1 = fmaf(w.z, z2.y, a1);
        a2 = fmaf(w.z, z2.z, a2); a3 = fmaf(w.z, z2.w, a3);
        a0 = fmaf(w.w, z3.x, a0); a1 = fmaf(w.w, z3.y, a1);
        a2 = fmaf(w.w, z3.z, a2); a3 = fmaf(w.w, z3.w, a3);
      }
      *reinterpret_cast<float4*>(pre2 + (khalf * RROWS + r) * Bn + bq * 4) =
          make_float4(a0, a1, a2, a3);
    }
    __syncthreads();

    // ---- gates + state update (128 threads: one (unit, b) each)
    if (tid < 128) {
      float g0, g1, g2, g3;
      {
        float xv0 = xg[((size_t)t * Gn + 0 * Hn + unit) * Bn + bb];
        float xv1 = xg[((size_t)t * Gn + 1 * Hn + unit) * Bn + bb];
        float xv2 = xg[((size_t)t * Gn + 2 * Hn + unit) * Bn + bb];
        float xv3 = xg[((size_t)t * Gn + 3 * Hn + unit) * Bn + bb];
        int rw0 = 0 * 4 + ju, rw1 = 1 * 4 + ju, rw2 = 2 * 4 + ju, rw3 = 3 * 4 + ju;
        g0 = pre2[rw0 * Bn + bb] + pre2[(RROWS + rw0) * Bn + bb] + xv0;
        g1 = pre2[rw1 * Bn + bb] + pre2[(RROWS + rw1) * Bn + bb] + xv1;
        g2 = pre2[rw2 * Bn + bb] + pre2[(RROWS + rw2) * Bn + bb] + xv2;
        g3 = pre2[rw3 * Bn + bb] + pre2[(RROWS + rw3) * Bn + bb] + xv3;
      }
      float gi = 1.f / (1.f + __expf(-g0));
      float gf = 1.f / (1.f + __expf(-g1));
      float gg = tanhf(g2);
      float go = 1.f / (1.f + __expf(-g3));
      c = gf * c + gi * gg;
      float h = go * tanhf(c);
      hout[((size_t)t * Hn + unit) * Bn + bb] = h;
      if (t == Tn - 1)
        out[(size_t)l * Bn * Hn + (size_t)bb * Hn + unit] = c;
    }

    // ---- grid barrier (skip after last step)
    if (t < Tn - 1) {
      unsigned sid = base + (unsigned)t + 1u;
      __threadfence();
      __syncthreads();
      if (tid == 0) *(volatile unsigned*)&g_flags[ct] = sid;
      bool ok;
      do {
        ok = (tid < NCTA) ? (*(volatile unsigned*)&g_flags[tid] >= sid) : true;
      } while (!__syncthreads_and(ok));
    }
  }
}

extern "C" void kernel_launch(void* const* d_in, const int* in_sizes, int n_in,
                              void* d_out, int out_size) {
  const float* x    = (const float*)d_in[0];
  const float* h0   = (const float*)d_in[1];
  const float* c0   = (const float*)d_in[2];
  const float* w_ih = (const float*)d_in[3];
  const float* w_hh = (const float*)d_in[4];
  const float* b_ih = (const float*)d_in[5];
  const float* b_hh = (const float*)d_in[6];
  float* out = (float*)d_out;

  cudaFuncSetAttribute(xg_gemm_kernel,
                       cudaFuncAttributeMaxDynamicSharedMemorySize, GEMM_SMEM);
  cudaFuncSetAttribute(lstm_rec_kernel,
                       cudaFuncAttributeMaxDynamicSharedMemorySize, REC_SMEM);

  init_kernel<<<1, 128>>>();
  for (int l = 0; l < Ln; l++) {
    xg_gemm_kernel<<<dim3(Tn / 4, Gn / TR), GT, GEMM_SMEM>>>(
        w_ih + (size_t)l * Gn * In, b_ih + (size_t)l * Gn, b_hh + (size_t)l * Gn,
        x, l ? 1 : 0, (l & 1) ^ 1);
    lstm_rec_kernel<<<NCTA, RTPB, REC_SMEM>>>(
        h0, c0, w_hh + (size_t)l * Gn * Hn, out, l, l & 1);
  }
}

// round 4
// speedup vs baseline: 1.6639x; 1.0911x over previous
#include <cuda_runtime.h>
#include <cuda_bf16.h>
#include <math.h>

#define Bn 32
#define Tn 2048
#define In 512
#define Hn 512
#define Ln 4
#define Gn 2048   // 4*H

// ---------------- phase A (xg pre-GEMM) config ----------------
#define GT 256
#define TR 128
#define TK 32
#define WPAD 132
#define ZPAD 132
#define GEMM_SMEM ((2*TK*WPAD + 2*TK*ZPAD) * 4)

// ---------------- recurrence config ----------------
#define NCTA 128
#define RTPB 512
#define KQn 4           // K-split ways
#define RROWS 16        // gate rows per CTA
#define WP 516
#define REC_SMEM ((RROWS*WP + Hn*Bn + KQn*RROWS*Bn) * 4)

// Static scratch
__device__ float g_xg[(size_t)Tn * Gn * Bn];       // [t][gate_row][b]
__device__ float g_hT[2][(size_t)Tn * Hn * Bn];    // ping-pong [t][j][b]
__device__ unsigned g_flags[NCTA];

__global__ void init_kernel() {
  if (threadIdx.x < NCTA) g_flags[threadIdx.x] = 0u;
}

// ============ Phase A: xg[t][gr][b] = sum_i W[gr][i]*inp[t][i][b] + bias ============
__global__ void __launch_bounds__(GT) xg_gemm_kernel(
    const float* __restrict__ W,
    const float* __restrict__ bih, const float* __restrict__ bhh,
    const float* __restrict__ x, int mode, int hin)
{
  extern __shared__ float sm[];
  float* Ws = sm;                  // [2][TK][WPAD]
  float* Zs = sm + 2 * TK * WPAD;  // [2][TK][ZPAD]

  const float* inp = mode ? g_hT[hin] : x;
  const int tid = threadIdx.x;
  const int t0 = blockIdx.x * 4;
  const int r0 = blockIdx.y * TR;
  const int trow = tid >> 4;
  const int tcol = tid & 15;

  float acc[8][8];
#pragma unroll
  for (int i = 0; i < 8; i++)
#pragma unroll
    for (int j = 0; j < 8; j++) acc[i][j] = 0.f;

  float4 wr[4], zr[4];

  auto ldg_chunk = [&](int kc) {
#pragma unroll
    for (int j = 0; j < 4; j++) {
      int idx = tid * 4 + j;
      int row = idx >> 3, kq = idx & 7;
      wr[j] = *reinterpret_cast<const float4*>(W + (size_t)(r0 + row) * In + kc + kq * 4);
    }
    if (mode) {
#pragma unroll
      for (int j = 0; j < 4; j++) {
        int kk = (tid >> 5) * 4 + j;
        int colq = tid & 31;
        int tt = colq >> 3, b4 = (colq & 7) * 4;
        zr[j] = *reinterpret_cast<const float4*>(inp + ((size_t)(t0 + tt) * In + kc + kk) * Bn + b4);
      }
    } else {
#pragma unroll
      for (int j = 0; j < 4; j++) {
        int idx = tid * 4 + j;
        int ki = idx & 7, tt = (idx >> 3) & 3, b = idx >> 5;
        zr[j] = *reinterpret_cast<const float4*>(inp + ((size_t)b * Tn + t0 + tt) * In + kc + ki * 4);
      }
    }
  };

  auto sts_chunk = [&](int buf) {
    float* Wb = Ws + buf * TK * WPAD;
    float* Zb = Zs + buf * TK * ZPAD;
#pragma unroll
    for (int j = 0; j < 4; j++) {
      int idx = tid * 4 + j;
      int row = idx >> 3, kq = idx & 7;
      Wb[(kq * 4 + 0) * WPAD + row] = wr[j].x;
      Wb[(kq * 4 + 1) * WPAD + row] = wr[j].y;
      Wb[(kq * 4 + 2) * WPAD + row] = wr[j].z;
      Wb[(kq * 4 + 3) * WPAD + row] = wr[j].w;
    }
    if (mode) {
#pragma unroll
      for (int j = 0; j < 4; j++) {
        int kk = (tid >> 5) * 4 + j;
        int colq = tid & 31;
        *reinterpret_cast<float4*>(Zb + kk * ZPAD + colq * 4) = zr[j];
      }
    } else {
#pragma unroll
      for (int j = 0; j < 4; j++) {
        int idx = tid * 4 + j;
        int ki = idx & 7, tt = (idx >> 3) & 3, b = idx >> 5;
        Zb[(ki * 4 + 0) * ZPAD + tt * 32 + b] = zr[j].x;
        Zb[(ki * 4 + 1) * ZPAD + tt * 32 + b] = zr[j].y;
        Zb[(ki * 4 + 2) * ZPAD + tt * 32 + b] = zr[j].z;
        Zb[(ki * 4 + 3) * ZPAD + tt * 32 + b] = zr[j].w;
      }
    }
  };

  auto compute = [&](int buf) {
    const float* Wb = Ws + buf * TK * WPAD;
    const float* Zb = Zs + buf * TK * ZPAD;
#pragma unroll 8
    for (int kk = 0; kk < TK; kk++) {
      float4 wa = *reinterpret_cast<const float4*>(Wb + kk * WPAD + trow * 8);
      float4 wb2 = *reinterpret_cast<const float4*>(Wb + kk * WPAD + trow * 8 + 4);
      float4 za = *reinterpret_cast<const float4*>(Zb + kk * ZPAD + tcol * 8);
      float4 zb2 = *reinterpret_cast<const float4*>(Zb + kk * ZPAD + tcol * 8 + 4);
      float w8[8] = {wa.x, wa.y, wa.z, wa.w, wb2.x, wb2.y, wb2.z, wb2.w};
      float z8[8] = {za.x, za.y, za.z, za.w, zb2.x, zb2.y, zb2.z, zb2.w};
#pragma unroll
      for (int i = 0; i < 8; i++)
#pragma unroll
        for (int j = 0; j < 8; j++)
          acc[i][j] = fmaf(w8[i], z8[j], acc[i][j]);
    }
  };

  const int NCH = In / TK;   // 16
  // pipeline: chunk0 -> smem; chunk1 -> regs; then 1 sync per iter
  ldg_chunk(0);
  sts_chunk(0);
  __syncthreads();
  ldg_chunk(TK);
  for (int c = 0; c < NCH; c++) {
    int buf = c & 1;
    if (c + 1 < NCH) sts_chunk(buf ^ 1);      // store regs (chunk c+1)
    if (c + 2 < NCH) ldg_chunk((c + 2) * TK); // fetch chunk c+2
    compute(buf);
    __syncthreads();
  }

#pragma unroll
  for (int i = 0; i < 8; i++) {
    int row = r0 + trow * 8 + i;
    float bv = __ldg(bih + row) + __ldg(bhh + row);
    int tt = tcol >> 2;
    int b0 = (tcol & 3) * 8;
    float* dst = g_xg + ((size_t)(t0 + tt) * Gn + row) * Bn + b0;
    float4 v0 = make_float4(acc[i][0] + bv, acc[i][1] + bv, acc[i][2] + bv, acc[i][3] + bv);
    float4 v1 = make_float4(acc[i][4] + bv, acc[i][5] + bv, acc[i][6] + bv, acc[i][7] + bv);
    *reinterpret_cast<float4*>(dst) = v0;
    *reinterpret_cast<float4*>(dst + 4) = v1;
  }
}

__device__ __forceinline__ float fsigm(float v) {
  return __fdividef(1.f, 1.f + __expf(-v));
}
__device__ __forceinline__ float ftanh(float v) {
  float e = __expf(-2.f * v);
  return __fdividef(1.f - e, 1.f + e);
}

// ============ Recurrence: h-path GEMM + gates, persistent per layer ============
__global__ void __launch_bounds__(RTPB, 1) lstm_rec_kernel(
    const float* __restrict__ h0, const float* __restrict__ c0,
    const float* __restrict__ Whh,
    float* __restrict__ out, int l, int hsel)
{
  extern __shared__ float smem[];
  float* Wsh = smem;                     // [16][WP]
  float* zsh = Wsh + RROWS * WP;         // [512][32]
  float* pre = zsh + Hn * Bn;            // [KQn][16][32]

  const int tid = threadIdx.x;
  const int ct = blockIdx.x;
  const int kq = tid >> 7;               // 0..3 K-quarter
  const int sub = tid & 127;
  const int r = sub >> 3;                // 0..15 gate row (local)
  const int bq = sub & 7;                // batch quad
  const int ju = tid >> 5;               // 0..3 (tid<128)
  const int bb = tid & 31;
  const int unit = ct * 4 + ju;

  float* hout = g_hT[hsel];
  const float* xg = g_xg;

  // load Whh slice
  for (int idx = tid; idx < RROWS * (Hn / 4); idx += RTPB) {
    int rr = idx >> 7, kk = idx & 127;
    int q = rr >> 2, juu = rr & 3;
    int gr = q * Hn + ct * 4 + juu;
    *reinterpret_cast<float4*>(Wsh + rr * WP + kk * 4) =
        *reinterpret_cast<const float4*>(Whh + (size_t)gr * Hn + kk * 4);
  }
  float c = (tid < 128) ? c0[(size_t)l * Bn * Hn + (size_t)bb * Hn + unit] : 0.f;

  const unsigned base = (unsigned)(l * Tn);

  for (int t = 0; t < Tn; t++) {
    // ---- prefetch xg (independent of other CTAs; hidden under staging+GEMM)
    float xv0 = 0.f, xv1 = 0.f, xv2 = 0.f, xv3 = 0.f;
    if (tid < 128) {
      const float* xp = xg + (size_t)t * Gn * Bn + (size_t)unit * Bn + bb;
      xv0 = __ldcg(xp);
      xv1 = __ldcg(xp + (size_t)Hn * Bn);
      xv2 = __ldcg(xp + (size_t)2 * Hn * Bn);
      xv3 = __ldcg(xp + (size_t)3 * Hn * Bn);
    }

    // ---- stage z = h_{t-1} [j][b] (reg-batched, L1-bypassed)
    if (t == 0) {
      const float* hs = h0 + (size_t)l * Bn * Hn;
      for (int idx = tid; idx < Bn * Hn; idx += RTPB) {
        int j = idx >> 5, b = idx & 31;
        zsh[j * Bn + b] = __ldcg(hs + (size_t)b * Hn + j);
      }
    } else {
      const float4* hs = reinterpret_cast<const float4*>(hout + (size_t)(t - 1) * Hn * Bn);
      float4* z4 = reinterpret_cast<float4*>(zsh);
      float4 v[8];
#pragma unroll
      for (int i = 0; i < 8; i++) v[i] = __ldcg(hs + tid + i * RTPB);
#pragma unroll
      for (int i = 0; i < 8; i++) z4[tid + i * RTPB] = v[i];
    }
    __syncthreads();

    // ---- quarter-K GEMM: pre[kq][16][32]
    {
      const float* wrow = Wsh + r * WP + kq * 128;
      const float* zq = zsh + kq * 128 * Bn + bq * 4;
      float a0 = 0.f, a1 = 0.f, a2 = 0.f, a3 = 0.f;
#pragma unroll 8
      for (int k = 0; k < 128; k += 4) {
        float4 w = *reinterpret_cast<const float4*>(wrow + k);
        float4 z0 = *reinterpret_cast<const float4*>(zq + (size_t)(k + 0) * Bn);
        float4 z1 = *reinterpret_cast<const float4*>(zq + (size_t)(k + 1) * Bn);
        float4 z2 = *reinterpret_cast<const float4*>(zq + (size_t)(k + 2) * Bn);
        float4 z3 = *reinterpret_cast<const float4*>(zq + (size_t)(k + 3) * Bn);
        a0 = fmaf(w.x, z0.x, a0); a1 = fmaf(w.x, z0.y, a1);
        a2 = fmaf(w.x, z0.z, a2); a3 = fmaf(w.x, z0.w, a3);
        a0 = fmaf(w.y, z1.x, a0); a1 = fmaf(w.y, z1.y, a1);
        a2 = fmaf(w.y, z1.z, a2); a3 = fmaf(w.y, z1.w, a3);
        a0 = fmaf(w.z, z2.x, a0); a1 = fmaf(w.z, z2.y, a1);
        a2 = fmaf(w.z, z2.z, a2); a3 = fmaf(w.z, z2.w, a3);
        a0 = fmaf(w.w, z3.x, a0); a1 = fmaf(w.w, z3.y, a1);
        a2 = fmaf(w.w, z3.z, a2); a3 = fmaf(w.w, z3.w, a3);
      }
      *reinterpret_cast<float4*>(pre + (kq * RROWS + r) * Bn + bq * 4) =
          make_float4(a0, a1, a2, a3);
    }
    __syncthreads();

    // ---- gates + state (tid<128: one (unit,b) each)
    if (tid < 128) {
      int rw0 = 0 * 4 + ju, rw1 = 1 * 4 + ju, rw2 = 2 * 4 + ju, rw3 = 3 * 4 + ju;
      float g0 = xv0, g1 = xv1, g2 = xv2, g3 = xv3;
#pragma unroll
      for (int q = 0; q < KQn; q++) {
        g0 += pre[(q * RROWS + rw0) * Bn + bb];
        g1 += pre[(q * RROWS + rw1) * Bn + bb];
        g2 += pre[(q * RROWS + rw2) * Bn + bb];
        g3 += pre[(q * RROWS + rw3) * Bn + bb];
      }
      float gi = fsigm(g0);
      float gf = fsigm(g1);
      float gg = ftanh(g2);
      float go = fsigm(g3);
      c = gf * c + gi * gg;
      float h = go * ftanh(c);
      hout[((size_t)t * Hn + unit) * Bn + bb] = h;
      if (t == Tn - 1)
        out[(size_t)l * Bn * Hn + (size_t)bb * Hn + unit] = c;
    }

    // ---- grid barrier: release store + warp-0 acquire poll
    if (t < Tn - 1) {
      unsigned sid = base + (unsigned)t + 1u;
      __syncthreads();
      if (tid == 0)
        asm volatile("st.release.gpu.global.b32 [%0], %1;"
                     :: "l"(g_flags + ct), "r"(sid) : "memory");
      if (tid < 32) {
        bool done;
        do {
          done = true;
#pragma unroll
          for (int q = 0; q < NCTA / 32; q++) {
            unsigned v;
            asm volatile("ld.acquire.gpu.global.b32 %0, [%1];"
                         : "=r"(v) : "l"(g_flags + q * 32 + tid) : "memory");
            done &= (v >= sid);
          }
        } while (!__all_sync(0xffffffffu, done));
      }
      __syncthreads();
    }
  }
}

extern "C" void kernel_launch(void* const* d_in, const int* in_sizes, int n_in,
                              void* d_out, int out_size) {
  const float* x    = (const float*)d_in[0];
  const float* h0   = (const float*)d_in[1];
  const float* c0   = (const float*)d_in[2];
  const float* w_ih = (const float*)d_in[3];
  const float* w_hh = (const float*)d_in[4];
  const float* b_ih = (const float*)d_in[5];
  const float* b_hh = (const float*)d_in[6];
  float* out = (float*)d_out;

  cudaFuncSetAttribute(xg_gemm_kernel,
                       cudaFuncAttributeMaxDynamicSharedMemorySize, GEMM_SMEM);
  cudaFuncSetAttribute(lstm_rec_kernel,
                       cudaFuncAttributeMaxDynamicSharedMemorySize, REC_SMEM);

  // launches: 0 init, 1 init (pad so ncu -s 5 profiles rec1 at index 5)
  init_kernel<<<1, 128>>>();
  init_kernel<<<1, 128>>>();
  for (int l = 0; l < Ln; l++) {
    xg_gemm_kernel<<<dim3(Tn / 4, Gn / TR), GT, GEMM_SMEM>>>(
        w_ih + (size_t)l * Gn * In, b_ih + (size_t)l * Gn, b_hh + (size_t)l * Gn,
        x, l ? 1 : 0, (l & 1) ^ 1);
    lstm_rec_kernel<<<NCTA, RTPB, REC_SMEM>>>(
        h0, c0, w_hh + (size_t)l * Gn * Hn, out, l, l & 1);
  }
}

// round 5
// speedup vs baseline: 1.9063x; 1.1457x over previous
#include <cuda_runtime.h>
#include <cuda_bf16.h>
#include <math.h>

#define Bn 32
#define Tn 2048
#define In 512
#define Hn 512
#define Ln 4
#define Gn 2048   // 4*H

// ---------------- phase A (xg pre-GEMM) config ----------------
#define GT 256
#define TR 128
#define TK 32
#define WPAD 132
#define ZPAD 132
#define GEMM_SMEM ((2*TK*WPAD + 2*TK*ZPAD) * 4)

// ---------------- recurrence config (batch-split groups) ----------------
#define NCTA 128
#define RTPB 512
#define NGRP 4          // batch groups
#define GCTA 32         // CTAs per group
#define GB 8            // batches per group
#define CROWS 64        // gate rows per CTA (4 gates x 16 units)
#define CUNITS 16
#define WPITCH 516
#define ZPITCH 516
#define REC_SMEM ((CROWS*WPITCH + GB*ZPITCH + 2*CROWS*GB) * 4)

// Static scratch
__device__ float g_xg[(size_t)Tn * Gn * Bn];       // [t][gate_row][b]
__device__ float g_hT[2][(size_t)Tn * Bn * Hn];    // ping-pong [t][b][j]
__device__ unsigned g_flags[NCTA];

__global__ void init_kernel() {
  if (threadIdx.x < NCTA) g_flags[threadIdx.x] = 0u;
}

// ============ Phase A: xg[t][gr][b] = sum_i W[gr][i]*inp[t][i или b][..] + bias ====
// mode 0: inp = x, layout (B, T, I). mode 1: inp = g_hT[hin], layout [t][b][i].
__global__ void __launch_bounds__(GT, 2) xg_gemm_kernel(
    const float* __restrict__ W,
    const float* __restrict__ bih, const float* __restrict__ bhh,
    const float* __restrict__ x, int mode, int hin)
{
  extern __shared__ float sm[];
  float* Ws = sm;                  // [2][TK][WPAD]
  float* Zs = sm + 2 * TK * WPAD;  // [2][TK][ZPAD]

  const float* inp = mode ? g_hT[hin] : x;
  const int tid = threadIdx.x;
  const int t0 = blockIdx.x * 4;
  const int r0 = blockIdx.y * TR;
  const int trow = tid >> 4;
  const int tcol = tid & 15;

  float acc[8][8];
#pragma unroll
  for (int i = 0; i < 8; i++)
#pragma unroll
    for (int j = 0; j < 8; j++) acc[i][j] = 0.f;

  float4 wr[4], zr[4];

  auto ldg_chunk = [&](int kc) {
#pragma unroll
    for (int j = 0; j < 4; j++) {
      int idx = tid * 4 + j;
      int row = idx >> 3, kq = idx & 7;
      wr[j] = *reinterpret_cast<const float4*>(W + (size_t)(r0 + row) * In + kc + kq * 4);
    }
#pragma unroll
    for (int j = 0; j < 4; j++) {
      int idx = tid * 4 + j;
      int ki = idx & 7, tt = (idx >> 3) & 3, b = idx >> 5;
      size_t base = mode ? ((size_t)(t0 + tt) * Bn + b) * In
                         : ((size_t)b * Tn + t0 + tt) * In;
      zr[j] = *reinterpret_cast<const float4*>(inp + base + kc + ki * 4);
    }
  };

  auto sts_chunk = [&](int buf) {
    float* Wb = Ws + buf * TK * WPAD;
    float* Zb = Zs + buf * TK * ZPAD;
#pragma unroll
    for (int j = 0; j < 4; j++) {
      int idx = tid * 4 + j;
      int row = idx >> 3, kq = idx & 7;
      Wb[(kq * 4 + 0) * WPAD + row] = wr[j].x;
      Wb[(kq * 4 + 1) * WPAD + row] = wr[j].y;
      Wb[(kq * 4 + 2) * WPAD + row] = wr[j].z;
      Wb[(kq * 4 + 3) * WPAD + row] = wr[j].w;
    }
#pragma unroll
    for (int j = 0; j < 4; j++) {
      int idx = tid * 4 + j;
      int ki = idx & 7, tt = (idx >> 3) & 3, b = idx >> 5;
      Zb[(ki * 4 + 0) * ZPAD + tt * 32 + b] = zr[j].x;
      Zb[(ki * 4 + 1) * ZPAD + tt * 32 + b] = zr[j].y;
      Zb[(ki * 4 + 2) * ZPAD + tt * 32 + b] = zr[j].z;
      Zb[(ki * 4 + 3) * ZPAD + tt * 32 + b] = zr[j].w;
    }
  };

  auto compute = [&](int buf) {
    const float* Wb = Ws + buf * TK * WPAD;
    const float* Zb = Zs + buf * TK * ZPAD;
#pragma unroll 8
    for (int kk = 0; kk < TK; kk++) {
      float4 wa = *reinterpret_cast<const float4*>(Wb + kk * WPAD + trow * 8);
      float4 wb2 = *reinterpret_cast<const float4*>(Wb + kk * WPAD + trow * 8 + 4);
      float4 za = *reinterpret_cast<const float4*>(Zb + kk * ZPAD + tcol * 8);
      float4 zb2 = *reinterpret_cast<const float4*>(Zb + kk * ZPAD + tcol * 8 + 4);
      float w8[8] = {wa.x, wa.y, wa.z, wa.w, wb2.x, wb2.y, wb2.z, wb2.w};
      float z8[8] = {za.x, za.y, za.z, za.w, zb2.x, zb2.y, zb2.z, zb2.w};
#pragma unroll
      for (int i = 0; i < 8; i++)
#pragma unroll
        for (int j = 0; j < 8; j++)
          acc[i][j] = fmaf(w8[i], z8[j], acc[i][j]);
    }
  };

  const int NCH = In / TK;   // 16
  ldg_chunk(0);
  sts_chunk(0);
  __syncthreads();
  ldg_chunk(TK);
  for (int c = 0; c < NCH; c++) {
    int buf = c & 1;
    if (c + 1 < NCH) sts_chunk(buf ^ 1);
    if (c + 2 < NCH) ldg_chunk((c + 2) * TK);
    compute(buf);
    __syncthreads();
  }

#pragma unroll
  for (int i = 0; i < 8; i++) {
    int row = r0 + trow * 8 + i;
    float bv = __ldg(bih + row) + __ldg(bhh + row);
    int tt = tcol >> 2;
    int b0 = (tcol & 3) * 8;
    float* dst = g_xg + ((size_t)(t0 + tt) * Gn + row) * Bn + b0;
    float4 v0 = make_float4(acc[i][0] + bv, acc[i][1] + bv, acc[i][2] + bv, acc[i][3] + bv);
    float4 v1 = make_float4(acc[i][4] + bv, acc[i][5] + bv, acc[i][6] + bv, acc[i][7] + bv);
    *reinterpret_cast<float4*>(dst) = v0;
    *reinterpret_cast<float4*>(dst + 4) = v1;
  }
}

__device__ __forceinline__ float fsigm(float v) {
  return __fdividef(1.f, 1.f + __expf(-v));
}
__device__ __forceinline__ float ftanh(float v) {
  float e = __expf(-2.f * v);
  return __fdividef(1.f - e, 1.f + e);
}

// ============ Recurrence: batch-split groups, per-group 32-CTA barrier ============
__global__ void __launch_bounds__(RTPB, 1) lstm_rec_kernel(
    const float* __restrict__ h0, const float* __restrict__ c0,
    const float* __restrict__ Whh,
    float* __restrict__ out, int l, int hsel)
{
  extern __shared__ float smem[];
  float* Wsh = smem;                       // [64][WPITCH]
  float* zsh = Wsh + CROWS * WPITCH;       // [8][ZPITCH]  z[b][j]
  float* pre = zsh + GB * ZPITCH;          // [2][64][8]

  const int tid = threadIdx.x;
  const int ct = blockIdx.x;
  const int grp = ct >> 5;                 // batch group 0..3
  const int cl = ct & 31;                  // CTA within group
  // GEMM mapping: (k-half, row, b-pair)
  const int kh = tid >> 8;                 // 0/1
  const int r = (tid >> 2) & 63;           // local gate row 0..63
  const int bp = tid & 3;                  // b and b+4
  // gates mapping (tid < 128): (unit, local batch)
  const int u = tid >> 3;                  // 0..15
  const int bl = tid & 7;                  // 0..7
  const int gb = grp * GB + bl;            // global batch
  const int unit = cl * CUNITS + u;        // global hidden unit

  float* hout = g_hT[hsel];
  const float* xg = g_xg;

  // load Whh slice: Wsh[rr][k], rr = q*16 + uu -> global row q*512 + cl*16 + uu
  for (int idx = tid; idx < CROWS * (Hn / 4); idx += RTPB) {
    int rr = idx >> 7, kk = idx & 127;
    int q = rr >> 4, uu = rr & 15;
    int gr = q * Hn + cl * CUNITS + uu;
    *reinterpret_cast<float4*>(Wsh + rr * WPITCH + kk * 4) =
        *reinterpret_cast<const float4*>(Whh + (size_t)gr * Hn + kk * 4);
  }
  float c = (tid < 128) ? c0[(size_t)l * Bn * Hn + (size_t)gb * Hn + unit] : 0.f;

  const unsigned base = (unsigned)(l * Tn);

  // xg prefetch regs (pipelined one step ahead)
  float xv0 = 0.f, xv1 = 0.f, xv2 = 0.f, xv3 = 0.f;
  if (tid < 128) {
    const float* xp = xg + ((size_t)0 * Gn + unit) * Bn + gb;
    xv0 = __ldcg(xp);
    xv1 = __ldcg(xp + (size_t)Hn * Bn);
    xv2 = __ldcg(xp + (size_t)2 * Hn * Bn);
    xv3 = __ldcg(xp + (size_t)3 * Hn * Bn);
  }

  for (int t = 0; t < Tn; t++) {
    // ---- stage z[b][j] = h_{t-1} for this group's 8 batches
    if (t == 0) {
      const float* hs = h0 + (size_t)l * Bn * Hn + (size_t)grp * GB * Hn;  // [8][512]
      const float4* h4 = reinterpret_cast<const float4*>(hs);
#pragma unroll
      for (int i = 0; i < 2; i++) {
        int idx = tid + i * RTPB;          // 0..1023 float4
        int b = idx >> 7, jj = idx & 127;
        float4 v = __ldcg(h4 + idx);
        *reinterpret_cast<float4*>(zsh + b * ZPITCH + jj * 4) = v;
      }
    } else {
      const float4* h4 = reinterpret_cast<const float4*>(
          hout + ((size_t)(t - 1) * Bn + grp * GB) * Hn);
      float4 v0 = __ldcg(h4 + tid);
      float4 v1 = __ldcg(h4 + tid + RTPB);
      {
        int b = tid >> 7, jj = tid & 127;
        *reinterpret_cast<float4*>(zsh + b * ZPITCH + jj * 4) = v0;
      }
      {
        int idx = tid + RTPB;
        int b = idx >> 7, jj = idx & 127;
        *reinterpret_cast<float4*>(zsh + b * ZPITCH + jj * 4) = v1;
      }
    }
    __syncthreads();

    // ---- prefetch xg for NEXT step (overlaps with GEMM)
    float nx0 = 0.f, nx1 = 0.f, nx2 = 0.f, nx3 = 0.f;
    if (tid < 128 && t + 1 < Tn) {
      const float* xp = xg + ((size_t)(t + 1) * Gn + unit) * Bn + gb;
      nx0 = __ldcg(xp);
      nx1 = __ldcg(xp + (size_t)Hn * Bn);
      nx2 = __ldcg(xp + (size_t)2 * Hn * Bn);
      nx3 = __ldcg(xp + (size_t)3 * Hn * Bn);
    }

    // ---- GEMM: pre[kh][r][bp], pre[kh][r][bp+4]; K-half per thread
    {
      const float* wrow = Wsh + r * WPITCH + kh * 256;
      const float* z0p = zsh + bp * ZPITCH + kh * 256;
      const float* z1p = z0p + 4 * ZPITCH;
      float a0 = 0.f, a1 = 0.f;
#pragma unroll 8
      for (int k = 0; k < 256; k += 4) {
        float4 w = *reinterpret_cast<const float4*>(wrow + k);
        float4 za = *reinterpret_cast<const float4*>(z0p + k);
        float4 zb = *reinterpret_cast<const float4*>(z1p + k);
        a0 = fmaf(w.x, za.x, a0); a1 = fmaf(w.x, zb.x, a1);
        a0 = fmaf(w.y, za.y, a0); a1 = fmaf(w.y, zb.y, a1);
        a0 = fmaf(w.z, za.z, a0); a1 = fmaf(w.z, zb.z, a1);
        a0 = fmaf(w.w, za.w, a0); a1 = fmaf(w.w, zb.w, a1);
      }
      pre[(kh * CROWS + r) * GB + bp] = a0;
      pre[(kh * CROWS + r) * GB + bp + 4] = a1;
    }
    __syncthreads();

    // ---- gates + state (tid<128)
    if (tid < 128) {
      float g0 = xv0 + pre[(0 * CROWS + 0 * CUNITS + u) * GB + bl]
                     + pre[(1 * CROWS + 0 * CUNITS + u) * GB + bl];
      float g1 = xv1 + pre[(0 * CROWS + 1 * CUNITS + u) * GB + bl]
                     + pre[(1 * CROWS + 1 * CUNITS + u) * GB + bl];
      float g2 = xv2 + pre[(0 * CROWS + 2 * CUNITS + u) * GB + bl]
                     + pre[(1 * CROWS + 2 * CUNITS + u) * GB + bl];
      float g3 = xv3 + pre[(0 * CROWS + 3 * CUNITS + u) * GB + bl]
                     + pre[(1 * CROWS + 3 * CUNITS + u) * GB + bl];
      float gi = fsigm(g0);
      float gf = fsigm(g1);
      float gg = ftanh(g2);
      float go = fsigm(g3);
      c = gf * c + gi * gg;
      float h = go * ftanh(c);
      hout[((size_t)t * Bn + gb) * Hn + unit] = h;
      if (t == Tn - 1)
        out[(size_t)l * Bn * Hn + (size_t)gb * Hn + unit] = c;
      xv0 = nx0; xv1 = nx1; xv2 = nx2; xv3 = nx3;
    }

    // ---- group barrier: release own flag, poll group's 32 flags (one line)
    if (t < Tn - 1) {
      unsigned sid = base + (unsigned)t + 1u;
      __syncthreads();
      if (tid == 0)
        asm volatile("st.release.gpu.global.b32 [%0], %1;"
                     :: "l"(g_flags + ct), "r"(sid) : "memory");
      if (tid < 32) {
        bool done;
        do {
          unsigned v;
          asm volatile("ld.acquire.gpu.global.b32 %0, [%1];"
                       : "=r"(v) : "l"(g_flags + (grp << 5) + tid) : "memory");
          done = (v >= sid);
        } while (!__all_sync(0xffffffffu, done));
      }
      __syncthreads();
    }
  }
}

extern "C" void kernel_launch(void* const* d_in, const int* in_sizes, int n_in,
                              void* d_out, int out_size) {
  const float* x    = (const float*)d_in[0];
  const float* h0   = (const float*)d_in[1];
  const float* c0   = (const float*)d_in[2];
  const float* w_ih = (const float*)d_in[3];
  const float* w_hh = (const float*)d_in[4];
  const float* b_ih = (const float*)d_in[5];
  const float* b_hh = (const float*)d_in[6];
  float* out = (float*)d_out;

  cudaFuncSetAttribute(xg_gemm_kernel,
                       cudaFuncAttributeMaxDynamicSharedMemorySize, GEMM_SMEM);
  cudaFuncSetAttribute(lstm_rec_kernel,
                       cudaFuncAttributeMaxDynamicSharedMemorySize, REC_SMEM);

  // pad launches so ncu -s 5 profiles a rec kernel
  init_kernel<<<1, 128>>>();
  init_kernel<<<1, 128>>>();
  for (int l = 0; l < Ln; l++) {
    xg_gemm_kernel<<<dim3(Tn / 4, Gn / TR), GT, GEMM_SMEM>>>(
        w_ih + (size_t)l * Gn * In, b_ih + (size_t)l * Gn, b_hh + (size_t)l * Gn,
        x, l ? 1 : 0, (l & 1) ^ 1);
    lstm_rec_kernel<<<NCTA, RTPB, REC_SMEM>>>(
        h0, c0, w_hh + (size_t)l * Gn * Hn, out, l, l & 1);
  }
}

// round 6
// speedup vs baseline: 1.9767x; 1.0370x over previous
#include <cuda_runtime.h>
#include <cuda_bf16.h>
#include <math.h>

#define Bn 32
#define Tn 2048
#define In 512
#define Hn 512
#define Ln 4
#define Gn 2048   // 4*H

// ---------------- phase A (xg pre-GEMM) config ----------------
#define GT 256
#define TR 128
#define TK 32
#define WPAD 132
#define ZPAD 132
#define GEMM_SMEM ((2*TK*WPAD + 2*TK*ZPAD) * 4)

// ---------------- recurrence config (batch-split groups) ----------------
#define NCTA 128
#define RTPB 512
#define NGRP 4          // batch groups
#define GCTA 32         // CTAs per group
#define GB 8            // batches per group
#define CROWS 64        // gate rows per CTA (4 gates x 16 units)
#define CUNITS 16
#define WPITCH 516
#define ZPITCH 516
#define REC_SMEM ((CROWS*WPITCH + GB*ZPITCH + 2*CROWS*GB) * 4)

// Static scratch
__device__ float g_xg[(size_t)Tn * Gn * Bn];       // [t][gate_row][b]
__device__ float g_hT[2][(size_t)Tn * Bn * Hn];    // ping-pong [t][b][j]
__device__ unsigned g_flags[NCTA];

__global__ void init_kernel() {
  if (threadIdx.x < NCTA) g_flags[threadIdx.x] = 0u;
}

// ============ Phase A: xg[t][gr][b] = sum_i W[gr][i]*inp + bias ============
// mode 0: inp = x, layout (B, T, I). mode 1: inp = g_hT[hin], layout [t][b][i].
__global__ void __launch_bounds__(GT, 2) xg_gemm_kernel(
    const float* __restrict__ W,
    const float* __restrict__ bih, const float* __restrict__ bhh,
    const float* __restrict__ x, int mode, int hin)
{
  extern __shared__ float sm[];
  float* Ws = sm;                  // [2][TK][WPAD]
  float* Zs = sm + 2 * TK * WPAD;  // [2][TK][ZPAD]

  const float* inp = mode ? g_hT[hin] : x;
  const int tid = threadIdx.x;
  const int t0 = blockIdx.x * 4;
  const int r0 = blockIdx.y * TR;
  const int trow = tid >> 4;
  const int tcol = tid & 15;

  float acc[8][8];
#pragma unroll
  for (int i = 0; i < 8; i++)
#pragma unroll
    for (int j = 0; j < 8; j++) acc[i][j] = 0.f;

  float4 wr[4], zr[4];

  auto ldg_chunk = [&](int kc) {
#pragma unroll
    for (int j = 0; j < 4; j++) {
      int idx = tid * 4 + j;
      int row = idx >> 3, kq = idx & 7;
      wr[j] = *reinterpret_cast<const float4*>(W + (size_t)(r0 + row) * In + kc + kq * 4);
    }
#pragma unroll
    for (int j = 0; j < 4; j++) {
      int idx = tid * 4 + j;
      int ki = idx & 7, tt = (idx >> 3) & 3, b = idx >> 5;
      size_t base = mode ? ((size_t)(t0 + tt) * Bn + b) * In
                         : ((size_t)b * Tn + t0 + tt) * In;
      zr[j] = *reinterpret_cast<const float4*>(inp + base + kc + ki * 4);
    }
  };

  auto sts_chunk = [&](int buf) {
    float* Wb = Ws + buf * TK * WPAD;
    float* Zb = Zs + buf * TK * ZPAD;
#pragma unroll
    for (int j = 0; j < 4; j++) {
      int idx = tid * 4 + j;
      int row = idx >> 3, kq = idx & 7;
      Wb[(kq * 4 + 0) * WPAD + row] = wr[j].x;
      Wb[(kq * 4 + 1) * WPAD + row] = wr[j].y;
      Wb[(kq * 4 + 2) * WPAD + row] = wr[j].z;
      Wb[(kq * 4 + 3) * WPAD + row] = wr[j].w;
    }
#pragma unroll
    for (int j = 0; j < 4; j++) {
      int idx = tid * 4 + j;
      int ki = idx & 7, tt = (idx >> 3) & 3, b = idx >> 5;
      Zb[(ki * 4 + 0) * ZPAD + tt * 32 + b] = zr[j].x;
      Zb[(ki * 4 + 1) * ZPAD + tt * 32 + b] = zr[j].y;
      Zb[(ki * 4 + 2) * ZPAD + tt * 32 + b] = zr[j].z;
      Zb[(ki * 4 + 3) * ZPAD + tt * 32 + b] = zr[j].w;
    }
  };

  auto compute = [&](int buf) {
    const float* Wb = Ws + buf * TK * WPAD;
    const float* Zb = Zs + buf * TK * ZPAD;
#pragma unroll 8
    for (int kk = 0; kk < TK; kk++) {
      float4 wa = *reinterpret_cast<const float4*>(Wb + kk * WPAD + trow * 8);
      float4 wb2 = *reinterpret_cast<const float4*>(Wb + kk * WPAD + trow * 8 + 4);
      float4 za = *reinterpret_cast<const float4*>(Zb + kk * ZPAD + tcol * 8);
      float4 zb2 = *reinterpret_cast<const float4*>(Zb + kk * ZPAD + tcol * 8 + 4);
      float w8[8] = {wa.x, wa.y, wa.z, wa.w, wb2.x, wb2.y, wb2.z, wb2.w};
      float z8[8] = {za.x, za.y, za.z, za.w, zb2.x, zb2.y, zb2.z, zb2.w};
#pragma unroll
      for (int i = 0; i < 8; i++)
#pragma unroll
        for (int j = 0; j < 8; j++)
          acc[i][j] = fmaf(w8[i], z8[j], acc[i][j]);
    }
  };

  const int NCH = In / TK;   // 16
  ldg_chunk(0);
  sts_chunk(0);
  __syncthreads();
  ldg_chunk(TK);
  for (int c = 0; c < NCH; c++) {
    int buf = c & 1;
    if (c + 1 < NCH) sts_chunk(buf ^ 1);
    if (c + 2 < NCH) ldg_chunk((c + 2) * TK);
    compute(buf);
    __syncthreads();
  }

#pragma unroll
  for (int i = 0; i < 8; i++) {
    int row = r0 + trow * 8 + i;
    float bv = __ldg(bih + row) + __ldg(bhh + row);
    int tt = tcol >> 2;
    int b0 = (tcol & 3) * 8;
    float* dst = g_xg + ((size_t)(t0 + tt) * Gn + row) * Bn + b0;
    float4 v0 = make_float4(acc[i][0] + bv, acc[i][1] + bv, acc[i][2] + bv, acc[i][3] + bv);
    float4 v1 = make_float4(acc[i][4] + bv, acc[i][5] + bv, acc[i][6] + bv, acc[i][7] + bv);
    *reinterpret_cast<float4*>(dst) = v0;
    *reinterpret_cast<float4*>(dst + 4) = v1;
  }
}

__device__ __forceinline__ float fsigm(float v) {
  return __fdividef(1.f, 1.f + __expf(-v));
}
__device__ __forceinline__ float ftanh(float v) {
  float e = __expf(-2.f * v);
  return __fdividef(1.f - e, 1.f + e);
}

// ============ Recurrence: batch-split groups, weak-poll barrier ============
__global__ void __launch_bounds__(RTPB, 1) lstm_rec_kernel(
    const float* __restrict__ h0, const float* __restrict__ c0,
    const float* __restrict__ Whh,
    float* __restrict__ out, int l, int hsel)
{
  extern __shared__ float smem[];
  float* Wsh = smem;                       // [64][WPITCH]
  float* zsh = Wsh + CROWS * WPITCH;       // [8][ZPITCH]  z[b][j]
  float* pre = zsh + GB * ZPITCH;          // [2][64][8]

  const int tid = threadIdx.x;
  const int ct = blockIdx.x;
  const int grp = ct >> 5;                 // batch group 0..3
  const int cl = ct & 31;                  // CTA within group
  // GEMM mapping: (k-half, row, b-pair)
  const int kh = tid >> 8;                 // 0/1
  const int r = (tid >> 2) & 63;           // local gate row 0..63
  const int bp = tid & 3;                  // b and b+4
  // gates mapping (tid < 128): (unit, local batch)
  const int u = tid >> 3;                  // 0..15
  const int bl = tid & 7;                  // 0..7
  const int gb = grp * GB + bl;            // global batch
  const int unit = cl * CUNITS + u;        // global hidden unit

  float* hout = g_hT[hsel];
  const float* xg = g_xg;

  // load Whh slice: rr = q*16 + uu -> global row q*512 + cl*16 + uu
  for (int idx = tid; idx < CROWS * (Hn / 4); idx += RTPB) {
    int rr = idx >> 7, kk = idx & 127;
    int q = rr >> 4, uu = rr & 15;
    int gr = q * Hn + cl * CUNITS + uu;
    *reinterpret_cast<float4*>(Wsh + rr * WPITCH + kk * 4) =
        *reinterpret_cast<const float4*>(Whh + (size_t)gr * Hn + kk * 4);
  }
  float c = (tid < 128) ? c0[(size_t)l * Bn * Hn + (size_t)gb * Hn + unit] : 0.f;

  const unsigned base = (unsigned)(l * Tn);
  const unsigned* myflags = g_flags + (grp << 5);

  // xg prefetch (pipelined one step ahead)
  float xv0 = 0.f, xv1 = 0.f, xv2 = 0.f, xv3 = 0.f;
  if (tid < 128) {
    const float* xp = xg + ((size_t)0 * Gn + unit) * Bn + gb;
    xv0 = __ldcg(xp);
    xv1 = __ldcg(xp + (size_t)Hn * Bn);
    xv2 = __ldcg(xp + (size_t)2 * Hn * Bn);
    xv3 = __ldcg(xp + (size_t)3 * Hn * Bn);
  }

  for (int t = 0; t < Tn; t++) {
    // ---- stage z[b][j] = h_{t-1} for this group's 8 batches
    if (t == 0) {
      const float* hs = h0 + (size_t)l * Bn * Hn + (size_t)grp * GB * Hn;
      const float4* h4 = reinterpret_cast<const float4*>(hs);
#pragma unroll
      for (int i = 0; i < 2; i++) {
        int idx = tid + i * RTPB;
        int b = idx >> 7, jj = idx & 127;
        float4 v = __ldcg(h4 + idx);
        *reinterpret_cast<float4*>(zsh + b * ZPITCH + jj * 4) = v;
      }
    } else {
      const float4* h4 = reinterpret_cast<const float4*>(
          hout + ((size_t)(t - 1) * Bn + grp * GB) * Hn);
      float4 v0 = __ldcg(h4 + tid);
      float4 v1 = __ldcg(h4 + tid + RTPB);
      {
        int b = tid >> 7, jj = tid & 127;
        *reinterpret_cast<float4*>(zsh + b * ZPITCH + jj * 4) = v0;
      }
      {
        int idx = tid + RTPB;
        int b = idx >> 7, jj = idx & 127;
        *reinterpret_cast<float4*>(zsh + b * ZPITCH + jj * 4) = v1;
      }
    }
    __syncthreads();

    // ---- prefetch xg for NEXT step (in flight through GEMM+gates)
    float nx0 = 0.f, nx1 = 0.f, nx2 = 0.f, nx3 = 0.f;
    if (tid < 128 && t + 1 < Tn) {
      const float* xp = xg + ((size_t)(t + 1) * Gn + unit) * Bn + gb;
      nx0 = __ldcg(xp);
      nx1 = __ldcg(xp + (size_t)Hn * Bn);
      nx2 = __ldcg(xp + (size_t)2 * Hn * Bn);
      nx3 = __ldcg(xp + (size_t)3 * Hn * Bn);
    }

    // ---- GEMM: pre[kh][r][bp], pre[kh][r][bp+4]
    {
      const float* wrow = Wsh + r * WPITCH + kh * 256;
      const float* z0p = zsh + bp * ZPITCH + kh * 256;
      const float* z1p = z0p + 4 * ZPITCH;
      float a0 = 0.f, a1 = 0.f;
#pragma unroll 8
      for (int k = 0; k < 256; k += 4) {
        float4 w = *reinterpret_cast<const float4*>(wrow + k);
        float4 za = *reinterpret_cast<const float4*>(z0p + k);
        float4 zb = *reinterpret_cast<const float4*>(z1p + k);
        a0 = fmaf(w.x, za.x, a0); a1 = fmaf(w.x, zb.x, a1);
        a0 = fmaf(w.y, za.y, a0); a1 = fmaf(w.y, zb.y, a1);
        a0 = fmaf(w.z, za.z, a0); a1 = fmaf(w.z, zb.z, a1);
        a0 = fmaf(w.w, za.w, a0); a1 = fmaf(w.w, zb.w, a1);
      }
      pre[(kh * CROWS + r) * GB + bp] = a0;
      pre[(kh * CROWS + r) * GB + bp + 4] = a1;
    }
    __syncthreads();

    // ---- gates + state (tid<128)
    if (tid < 128) {
      float g0 = xv0 + pre[(0 * CROWS + 0 * CUNITS + u) * GB + bl]
                     + pre[(1 * CROWS + 0 * CUNITS + u) * GB + bl];
      float g1 = xv1 + pre[(0 * CROWS + 1 * CUNITS + u) * GB + bl]
                     + pre[(1 * CROWS + 1 * CUNITS + u) * GB + bl];
      float g2 = xv2 + pre[(0 * CROWS + 2 * CUNITS + u) * GB + bl]
                     + pre[(1 * CROWS + 2 * CUNITS + u) * GB + bl];
      float g3 = xv3 + pre[(0 * CROWS + 3 * CUNITS + u) * GB + bl]
                     + pre[(1 * CROWS + 3 * CUNITS + u) * GB + bl];
      float gi = fsigm(g0);
      float gf = fsigm(g1);
      float gg = ftanh(g2);
      float go = fsigm(g3);
      c = gf * c + gi * gg;
      float h = go * ftanh(c);
      hout[((size_t)t * Bn + gb) * Hn + unit] = h;
      if (t == Tn - 1)
        out[(size_t)l * Bn * Hn + (size_t)gb * Hn + unit] = c;
      xv0 = nx0; xv1 = nx1; xv2 = nx2; xv3 = nx3;
    }

    // ---- group barrier: relaxed flag + hoisted fences
    //   producer: bar -> fence.acq_rel.gpu -> st.relaxed
    //   consumer: relaxed poll loop (no per-iter ordering) -> one fence -> bar
    if (t < Tn - 1) {
      unsigned sid = base + (unsigned)t + 1u;
      __syncthreads();
      if (tid == 0) {
        asm volatile("fence.acq_rel.gpu;" ::: "memory");
        asm volatile("st.relaxed.gpu.global.b32 [%0], %1;"
                     :: "l"(g_flags + ct), "r"(sid) : "memory");
      }
      if (tid < 32) {
        bool done;
        do {
          unsigned v;
          asm volatile("ld.relaxed.gpu.global.b32 %0, [%1];"
                       : "=r"(v) : "l"(myflags + tid) : "memory");
          done = (v >= sid);
        } while (!__all_sync(0xffffffffu, done));
        asm volatile("fence.acq_rel.gpu;" ::: "memory");
      }
      __syncthreads();
    }
  }
}

extern "C" void kernel_launch(void* const* d_in, const int* in_sizes, int n_in,
                              void* d_out, int out_size) {
  const float* x    = (const float*)d_in[0];
  const float* h0   = (const float*)d_in[1];
  const float* c0   = (const float*)d_in[2];
  const float* w_ih = (const float*)d_in[3];
  const float* w_hh = (const float*)d_in[4];
  const float* b_ih = (const float*)d_in[5];
  const float* b_hh = (const float*)d_in[6];
  float* out = (float*)d_out;

  cudaFuncSetAttribute(xg_gemm_kernel,
                       cudaFuncAttributeMaxDynamicSharedMemorySize, GEMM_SMEM);
  cudaFuncSetAttribute(lstm_rec_kernel,
                       cudaFuncAttributeMaxDynamicSharedMemorySize, REC_SMEM);

  // pad launches so ncu -s 5 profiles a rec kernel
  init_kernel<<<1, 128>>>();
  init_kernel<<<1, 128>>>();
  for (int l = 0; l < Ln; l++) {
    xg_gemm_kernel<<<dim3(Tn / 4, Gn / TR), GT, GEMM_SMEM>>>(
        w_ih + (size_t)l * Gn * In, b_ih + (size_t)l * Gn, b_hh + (size_t)l * Gn,
        x, l ? 1 : 0, (l & 1) ^ 1);
    lstm_rec_kernel<<<NCTA, RTPB, REC_SMEM>>>(
        h0, c0, w_hh + (size_t)l * Gn * Hn, out, l, l & 1);
  }
}